// round 17
// baseline (speedup 1.0000x reference)
#include <cuda_runtime.h>
#include <math_constants.h>
#include <cstdint>

// WorkingMemory, uncentered algebraic form (values bounded, fp32-safe):
//   raw[j] = sum_k(bit?a0:a1);  T = (sum_{hi} exp(raw))/512
//   e_i = exp(raw_i) + T;  S = sum e;  ssq = sum e^2
//   r{0,1}[b,c] = log( sum_i e_i*(S-e_i)*exp(m{0,1}[b,i,c]) + exp(v{0,1}[b,c])*ssq )
//
// R17 (= R16 resubmit; R16 was an infra timeout):
// wm_main identical to R14 (measured ~46.6us: one wave of 592x512,
// fractional unit ranges, no fences/ldcs in the hot loop). Tail kernel
// reshaped 591x64 -> 74x512 (8 boundaries per CTA, full warps) to cut its
// 4.7us cost to ~1.5-2us.

#define BB 1024
#define AA 512
#define CC 64
#define DD 10
#define NTH 512
#define G1 592             // 148 SMs * 4 CTAs, one wave
#define NPAIR (2 * BB)     // 2048 (b,m) pairs
#define UPP 16             // units per pair
#define UTOT (NPAIR * UPP) // 32768 units

__device__ float g_part[NPAIR][2][CC];
__device__ float g_ssq[NPAIR];

__device__ __forceinline__ float redSum512(float v, float* sbuf) {
    #pragma unroll
    for (int o = 16; o; o >>= 1) v += __shfl_xor_sync(0xffffffffu, v, o);
    int w = threadIdx.x >> 5;
    if ((threadIdx.x & 31) == 0) sbuf[w] = v;
    __syncthreads();
    if (threadIdx.x < 32) {
        float x = (threadIdx.x < 16) ? sbuf[threadIdx.x] : 0.0f;
        #pragma unroll
        for (int o = 8; o; o >>= 1) x += __shfl_xor_sync(0xffffffffu, x, o);
        if (threadIdx.x == 0) sbuf[0] = x;
    }
    __syncthreads();
    float r = sbuf[0];
    __syncthreads();
    return r;
}

// phase 1, 512 threads: fills sw[512] = e*(S-e), returns ssq. 3 reductions only.
__device__ __forceinline__ void phase1(int b, const float* __restrict__ a0,
                                       const float* __restrict__ a1,
                                       float* sw, float* sred, float& ssq_out) {
    const int tid = threadIdx.x;
    float base = 0.0f, diff[DD];
    const float* pa0 = a0 + b * DD;
    const float* pa1 = a1 + b * DD;
    #pragma unroll
    for (int k = 0; k < DD; k++) {
        float x1 = pa1[k];
        base += x1;
        diff[k] = pa0[k] - x1;
    }
    const int jlo = tid, jhi = tid + AA;
    float rlo = base, rhi = base;
    #pragma unroll
    for (int k = 0; k < DD; k++) {
        int sh = 9 - k;
        if ((jlo >> sh) & 1) rlo += diff[k];
        if ((jhi >> sh) & 1) rhi += diff[k];
    }
    float sumh = redSum512(__expf(rhi), sred);
    float T = sumh * (1.0f / 512.0f);          // exp(y2)
    float e = __expf(rlo) + T;                 // exp(attn_i), no log round-trip
    float S = redSum512(e, sred);
    ssq_out = redSum512(e * e, sred);
    sw[tid] = e * (S - e);
    __syncthreads();
}

__global__ __launch_bounds__(NTH, 4)
void wm_main(const float* __restrict__ m0, const float* __restrict__ m1,
             const float* __restrict__ a0, const float* __restrict__ a1,
             const float* __restrict__ v0, const float* __restrict__ v1,
             float* __restrict__ out)
{
    __shared__ float sred[32];
    __shared__ float sw[AA];
    __shared__ __align__(16) float racc[32][68];   // [row-group][channel], padded

    const int k   = blockIdx.x;
    const int tid = threadIdx.x;
    const int u0 = (int)(((long long)k * UTOT) / G1);
    const int u1 = (int)(((long long)(k + 1) * UTOT) / G1);
    const int c4 = tid & 15;      // float4 channel block (0..15)
    const int rg = tid >> 4;      // row within unit (0..31)

    int cur_b = -1;
    float ssq = 0.0f;
    int u = u0;

    while (u < u1) {
        const int p    = u >> 4;
        const int b    = p >> 1;
        const int m    = p & 1;
        const int pend = (p + 1) << 4;
        const int run  = min(u1, pend) - u;

        if (b != cur_b) { phase1(b, a0, a1, sw, sred, ssq); cur_b = b; }

        const float4* src = (const float4*)(m ? m1 : m0) + ((size_t)b << 13);
        const int row0 = (u & 15) << 5;    // starting row of this span

        float4 acc = make_float4(0.f, 0.f, 0.f, 0.f);
        #pragma unroll 4
        for (int j = 0; j < run; j++) {
            const int row = row0 + j * 32 + rg;
            float  w = sw[row];
            float4 x = src[row * 16 + c4];
            acc.x = fmaf(w, __expf(x.x), acc.x);
            acc.y = fmaf(w, __expf(x.y), acc.y);
            acc.z = fmaf(w, __expf(x.z), acc.z);
            acc.w = fmaf(w, __expf(x.w), acc.w);
        }
        u += run;

        // flush this pair's contribution
        __syncthreads();                       // racc reuse guard
        *reinterpret_cast<float4*>(&racc[rg][c4 * 4]) = acc;
        __syncthreads();

        const bool is_start = (p << 4) >= u0;
        const bool is_end   = (pend <= u1);
        if (tid < CC) {
            float s = 0.0f;
            #pragma unroll
            for (int g = 0; g < 32; g++) s += racc[g][tid];
            if (is_start && is_end) {
                const float* vv = m ? v1 : v0;
                out[((size_t)m * BB + b) * CC + tid] =
                    __logf(s + __expf(vv[b * CC + tid]) * ssq);
            } else if (is_start) {
                g_part[p][0][tid] = s;         // end-CTA's half combined later
            } else {
                g_part[p][1][tid] = s;         // cleanup kernel finalizes
                if (tid == 0) g_ssq[p] = ssq;
            }
        }
    }
}

// finalize the <=591 boundary-split pairs.
// 74 CTAs x 512 threads: 8 boundaries per CTA, 64 channels per boundary.
__global__ __launch_bounds__(512)
void wm_split(const float* __restrict__ v0, const float* __restrict__ v1,
              float* __restrict__ out)
{
    const int kk = blockIdx.x * 8 + (threadIdx.x >> 6) + 1;   // boundary 1..592
    if (kk >= G1) return;
    const int u0b = (int)(((long long)kk * UTOT) / G1);
    if ((u0b & 15) == 0) return;               // boundary aligned: no split pair
    const int p = u0b >> 4;
    const int b = p >> 1;
    const int m = p & 1;
    const int c = threadIdx.x & 63;
    float s = g_part[p][0][c] + g_part[p][1][c];
    float ssq = g_ssq[p];
    const float* vv = m ? v1 : v0;
    out[((size_t)m * BB + b) * CC + c] = __logf(s + __expf(vv[b * CC + c]) * ssq);
}

extern "C" void kernel_launch(void* const* d_in, const int* in_sizes, int n_in,
                              void* d_out, int out_size) {
    const float* m0 = (const float*)d_in[0];
    const float* m1 = (const float*)d_in[1];
    const float* a0 = (const float*)d_in[2];
    const float* a1 = (const float*)d_in[3];
    const float* v0 = (const float*)d_in[4];
    const float* v1 = (const float*)d_in[5];
    float* out = (float*)d_out;
    wm_main<<<G1, NTH>>>(m0, m1, a0, a1, v0, v1, out);
    wm_split<<<74, 512>>>(v0, v1, out);
}